// round 10
// baseline (speedup 1.0000x reference)
#include <cuda_runtime.h>
#include <cuda_bf16.h>
#include <cstdint>

// Problem constants (fixed by the dataset).
#define Nn 100000
#define Ee 1600000
#define IN_F 128
#define H_F 64
#define OUT_F 32

static_assert(Nn % 32 == 0, "row tiling assumes N % 32 == 0");

// Scratch (static __device__ — no allocation allowed).
// NOTE: these symbols must ONLY be referenced from device code. Passing them
// as kernel arguments from host code yields the host shadow address, which on
// GB300 (ATS) silently dereferences host memory instead of faulting.
__device__ __align__(256) float g_deg [Nn];
__device__ __align__(256) float g_dinv[Nn];
__device__ __align__(256) float g_y   [(size_t)Nn * H_F];
__device__ __align__(256) float g_z   [(size_t)Nn * H_F];
__device__ __align__(256) float g_acc1[(size_t)Nn * H_F];
__device__ __align__(256) float g_acc2[(size_t)Nn * H_F];
__device__ __align__(256) int   g_src [Ee];
__device__ __align__(256) int   g_dst [Ee];
__device__ int g_is64;

// ---------------------------------------------------------------------------
// KD: detect edge_index dtype. For int64 node ids < 2^31 (little-endian),
// every odd 32-bit word of the first 2048 entries is 0. For int32, those
// words are random node ids (all-zero probability ~0). One block.
__global__ void k_detect(const int* __restrict__ ei) {
    __shared__ int nz;
    if (threadIdx.x == 0) nz = 0;
    __syncthreads();
    int acc = 0;
#pragma unroll
    for (int k = 0; k < 8; k++) {
        int i = threadIdx.x * 8 + k;      // i in [0, 2048)
        acc |= ei[2 * i + 1];             // word 4095 max — in bounds for both
    }
    if (acc) atomicOr(&nz, 1);
    __syncthreads();
    if (threadIdx.x == 0) g_is64 = (nz == 0) ? 1 : 0;
}

// KC: convert indices to clean int32 arrays (handles both dtypes).
__global__ void k_cvt(const void* __restrict__ ei, int E) {
    int e = blockIdx.x * blockDim.x + threadIdx.x;
    if (e >= E) return;
    if (g_is64) {
        const long long* p = (const long long*)ei;
        g_src[e] = (int)p[e];
        g_dst[e] = (int)p[E + e];
    } else {
        const int* p = (const int*)ei;
        g_src[e] = p[e];
        g_dst[e] = p[E + e];
    }
}

// ---------------------------------------------------------------------------
// K0: zero accumulators, deg = 1 (self loop)
__global__ void k_init() {
    int i = blockIdx.x * blockDim.x + threadIdx.x;
    if (i < Nn * H_F) { g_acc1[i] = 0.f; g_acc2[i] = 0.f; }
    if (i < Nn) g_deg[i] = 1.0f;
}

// K1: in-degree count
__global__ void k_deg(int E) {
    int e = blockIdx.x * blockDim.x + threadIdx.x;
    if (e < E) atomicAdd(&g_deg[g_dst[e]], 1.0f);
}

// K2: dinv = rsqrt(deg)
__global__ void k_dinv() {
    int n = blockIdx.x * blockDim.x + threadIdx.x;
    if (n < Nn) g_dinv[n] = rsqrtf(g_deg[n]);
}

// ---------------------------------------------------------------------------
// K3: y = dinv ⊙ (x @ W1).  Block: 32 rows × 64 cols, 128 threads,
// thread tile 4x4, full K=128 staged in smem. 48KB static smem.
__global__ __launch_bounds__(128) void k_gemm1(const float* __restrict__ x,
                                               const float* __restrict__ W1) {
    __shared__ float xs[32 * 128];   // 16 KB, row-major [m][k]
    __shared__ float ws[128 * 64];   // 32 KB, row-major [k][j]
    int tid = threadIdx.x;
    size_t rowbase = (size_t)blockIdx.x * 32;

    const float4* x4 = (const float4*)(x + rowbase * IN_F);
    float4* xs4 = (float4*)xs;
#pragma unroll
    for (int it = 0; it < 8; it++) xs4[tid + it * 128] = x4[tid + it * 128];
    const float4* w4 = (const float4*)W1;
    float4* ws4 = (float4*)ws;
#pragma unroll
    for (int it = 0; it < 16; it++) ws4[tid + it * 128] = w4[tid + it * 128];
    __syncthreads();

    int jg = tid & 15, mg = tid >> 4;
    int j0 = jg * 4, m0 = mg * 4;
    float acc[4][4] = {};
#pragma unroll 8
    for (int k = 0; k < 128; k++) {
        float4 b = *(const float4*)&ws[k * 64 + j0];
#pragma unroll
        for (int i = 0; i < 4; i++) {
            float a = xs[(m0 + i) * 128 + k];
            acc[i][0] += a * b.x; acc[i][1] += a * b.y;
            acc[i][2] += a * b.z; acc[i][3] += a * b.w;
        }
    }
#pragma unroll
    for (int i = 0; i < 4; i++) {
        size_t row = rowbase + m0 + i;
        float dv = g_dinv[row];
        float4 o = make_float4(acc[i][0] * dv, acc[i][1] * dv,
                               acc[i][2] * dv, acc[i][3] * dv);
        *(float4*)&g_y[row * H_F + j0] = o;
    }
}

// ---------------------------------------------------------------------------
// K4/K6: edge propagate. One thread per (edge, float4-chunk): 16 threads
// cover one edge's 64 features. Coalesced float4 gather + 4 scalar
// atomicAdds (return unused -> REDG, spread consecutive addresses).
// PASS=0: g_y -> g_acc1.  PASS=1: g_z -> g_acc2.  Globals referenced in
// device code only (host symbol-passing is the ATS trap).
template <int PASS>
__global__ void k_prop(int E) {
    int idx = blockIdx.x * blockDim.x + threadIdx.x;
    if (idx >= E * 16) return;
    int e = idx >> 4, c = idx & 15;
    int s = __ldg(&g_src[e]);
    int d = __ldg(&g_dst[e]);
    const float* val = (PASS == 0) ? g_y : g_z;
    float*       acc = (PASS == 0) ? g_acc1 : g_acc2;
    float4 v = *(const float4*)(val + (size_t)s * H_F + c * 4);
    float* p = acc + (size_t)d * H_F + c * 4;
    atomicAdd(p + 0, v.x);
    atomicAdd(p + 1, v.y);
    atomicAdd(p + 2, v.z);
    atomicAdd(p + 3, v.w);
}

// ---------------------------------------------------------------------------
// K5: z = dinv ⊙ relu(dinv·(acc1 + y) + b1)
__global__ void k_relu(const float* __restrict__ b1) {
    int i = blockIdx.x * blockDim.x + threadIdx.x;
    if (i >= Nn * H_F) return;
    int n = i >> 6, f = i & 63;
    float dv = g_dinv[n];
    float h = fmaf(dv, g_acc1[i] + g_y[i], b1[f]);
    h = fmaxf(h, 0.0f);
    g_z[i] = dv * h;
}

// ---------------------------------------------------------------------------
// K7: g = dinv·(acc2 + z);  mu = g@Wmu + bmu;  log = g@Wlog + blog.
// Block: 32 nodes, 128 threads, thread tile 4x4 over [32 x 64] outputs
// (cols 0..31 = mu, 32..63 = log).
__global__ __launch_bounds__(128) void k_final(const float* __restrict__ Wmu,
                                               const float* __restrict__ bmu,
                                               const float* __restrict__ Wlog,
                                               const float* __restrict__ blog,
                                               float* __restrict__ out) {
    __shared__ float gs[32 * 64];   // 8 KB
    __shared__ float wc[64 * 64];   // 16 KB, [k][j]
    __shared__ float bc[64];
    int tid = threadIdx.x;
    size_t nb = (size_t)blockIdx.x * 32;

    for (int i = tid; i < 64 * 64; i += 128) {
        int k = i >> 6, j = i & 63;
        wc[i] = (j < 32) ? Wmu[k * 32 + j] : Wlog[k * 32 + (j - 32)];
    }
    if (tid < 64) bc[tid] = (tid < 32) ? bmu[tid] : blog[tid - 32];
    for (int i = tid; i < 32 * 64; i += 128) {
        size_t n = nb + (i >> 6);
        size_t off = n * H_F + (i & 63);
        gs[i] = g_dinv[n] * (g_acc2[off] + g_z[off]);
    }
    __syncthreads();

    int jg = tid & 15, mg = tid >> 4;
    int j0 = jg * 4, m0 = mg * 4;
    float acc[4][4] = {};
#pragma unroll 8
    for (int k = 0; k < 64; k++) {
        float4 b = *(const float4*)&wc[k * 64 + j0];
#pragma unroll
        for (int i = 0; i < 4; i++) {
            float a = gs[(m0 + i) * 64 + k];
            acc[i][0] += a * b.x; acc[i][1] += a * b.y;
            acc[i][2] += a * b.z; acc[i][3] += a * b.w;
        }
    }
#pragma unroll
    for (int i = 0; i < 4; i++) {
        size_t n = nb + m0 + i;
        float4 o = make_float4(acc[i][0] + bc[j0], acc[i][1] + bc[j0 + 1],
                               acc[i][2] + bc[j0 + 2], acc[i][3] + bc[j0 + 3]);
        float* dp = (j0 < 32)
            ? (out + n * OUT_F + j0)
            : (out + (size_t)Nn * OUT_F + n * OUT_F + (j0 - 32));
        *(float4*)dp = o;
    }
}

// ---------------------------------------------------------------------------
extern "C" void kernel_launch(void* const* d_in, const int* in_sizes, int n_in,
                              void* d_out, int out_size) {
    const float* x    = (const float*)d_in[0];
    const void*  ei   = d_in[1];                 // [2, E] int32 OR int64
    const float* W1   = (const float*)d_in[2];
    const float* b1   = (const float*)d_in[3];
    const float* Wmu  = (const float*)d_in[4];
    const float* bmu  = (const float*)d_in[5];
    const float* Wlog = (const float*)d_in[6];
    const float* blog = (const float*)d_in[7];
    float*       out  = (float*)d_out;

    int E = in_sizes[1] / 2;

    k_detect<<<1, 256>>>((const int*)ei);
    k_cvt<<<(E + 255) / 256, 256>>>(ei, E);
    k_init<<<(Nn * H_F + 255) / 256, 256>>>();
    k_deg<<<(E + 255) / 256, 256>>>(E);
    k_dinv<<<(Nn + 255) / 256, 256>>>();
    k_gemm1<<<Nn / 32, 128>>>(x, W1);
    {
        int blocks = (E * 16 + 255) / 256;
        k_prop<0><<<blocks, 256>>>(E);
    }
    k_relu<<<(Nn * H_F + 255) / 256, 256>>>(b1);
    {
        int blocks = (E * 16 + 255) / 256;
        k_prop<1><<<blocks, 256>>>(E);
    }
    k_final<<<Nn / 32, 128>>>(Wmu, bmu, Wlog, blog, out);
}

// round 12
// speedup vs baseline: 2.2459x; 2.2459x over previous
#include <cuda_runtime.h>
#include <cuda_bf16.h>
#include <cstdint>

// Problem constants (fixed by the dataset).
#define Nn 100000
#define Ee 1600000
#define IN_F 128
#define H_F 64
#define OUT_F 32
#define NB 391            // ceil(Nn/256)

static_assert(Nn % 32 == 0, "row tiling assumes N % 32 == 0");

// Scratch (static __device__ — no allocation allowed).
// NOTE: referenced ONLY from device code (host symbol-passing is the ATS trap
// that silently reads host shadows on GB300).
__device__ __align__(256) float g_dinv[Nn];
__device__ __align__(256) float g_y   [(size_t)Nn * H_F];
__device__ __align__(256) float g_z   [(size_t)Nn * H_F];
__device__ __align__(256) float g_g   [(size_t)Nn * H_F];
__device__ __align__(256) int   g_src [Ee];
__device__ __align__(256) int   g_dst [Ee];
__device__ __align__(256) int   g_eidx[Ee];       // CSR: src ids grouped by dst
__device__ __align__(256) int   g_cnt [Nn];
__device__ __align__(256) int   g_off [Nn];
__device__ __align__(256) int   g_cur [Nn];
__device__ __align__(256) int   g_bsum[NB];
__device__ __align__(256) int   g_bpre[NB];
__device__ int g_is64;

// ---------------------------------------------------------------------------
// KD: detect edge_index dtype (int64 ids < 2^31 -> odd 32-bit words all 0).
__global__ void k_detect(const int* __restrict__ ei) {
    __shared__ int nz;
    if (threadIdx.x == 0) nz = 0;
    __syncthreads();
    int acc = 0;
#pragma unroll
    for (int k = 0; k < 8; k++) {
        int i = threadIdx.x * 8 + k;      // [0, 2048)
        acc |= ei[2 * i + 1];
    }
    if (acc) atomicOr(&nz, 1);
    __syncthreads();
    if (threadIdx.x == 0) g_is64 = (nz == 0) ? 1 : 0;
}

// KZ: zero the histogram (graph replays reuse state; must re-zero each call).
__global__ void k_zero() {
    int i = blockIdx.x * blockDim.x + threadIdx.x;
    if (i < Nn) g_cnt[i] = 0;
}

// KC: convert indices to int32 + in-degree histogram (fused).
__global__ void k_cvt_hist(const void* __restrict__ ei, int E) {
    int e = blockIdx.x * blockDim.x + threadIdx.x;
    if (e >= E) return;
    int s, d;
    if (g_is64) {
        const long long* p = (const long long*)ei;
        s = (int)p[e]; d = (int)p[E + e];
    } else {
        const int* p = (const int*)ei;
        s = p[e]; d = p[E + e];
    }
    g_src[e] = s;
    g_dst[e] = d;
    atomicAdd(&g_cnt[d], 1);
}

// ---------------------------------------------------------------------------
// S1: per-256-tile exclusive scan of g_cnt -> g_off, tile totals -> g_bsum.
__global__ void k_scan1() {
    __shared__ int sh[256];
    int i = blockIdx.x * 256 + threadIdx.x;
    int v = (i < Nn) ? g_cnt[i] : 0;
    sh[threadIdx.x] = v;
    __syncthreads();
#pragma unroll
    for (int off = 1; off < 256; off <<= 1) {
        int t = (threadIdx.x >= off) ? sh[threadIdx.x - off] : 0;
        __syncthreads();
        sh[threadIdx.x] += t;
        __syncthreads();
    }
    if (i < Nn) g_off[i] = sh[threadIdx.x] - v;     // exclusive
    if (threadIdx.x == 255) g_bsum[blockIdx.x] = sh[255];
}

// S2: single-block exclusive scan of the NB tile totals.
__global__ void k_scan2() {
    __shared__ int sh[512];
    int v = (threadIdx.x < NB) ? g_bsum[threadIdx.x] : 0;
    sh[threadIdx.x] = v;
    __syncthreads();
#pragma unroll
    for (int off = 1; off < 512; off <<= 1) {
        int t = (threadIdx.x >= off) ? sh[threadIdx.x - off] : 0;
        __syncthreads();
        sh[threadIdx.x] += t;
        __syncthreads();
    }
    if (threadIdx.x < NB) g_bpre[threadIdx.x] = sh[threadIdx.x] - v;
}

// S3: finalize offsets; zero cursors; dinv = rsqrt(deg+1) (self loop).
__global__ void k_scan3() {
    int i = blockIdx.x * blockDim.x + threadIdx.x;
    if (i >= Nn) return;
    g_off[i] += g_bpre[blockIdx.x];
    g_cur[i] = 0;
    g_dinv[i] = rsqrtf((float)g_cnt[i] + 1.0f);
}

// KS: scatter src ids into dst-grouped CSR slots.
__global__ void k_scatter(int E) {
    int e = blockIdx.x * blockDim.x + threadIdx.x;
    if (e >= E) return;
    int d = g_dst[e];
    int pos = g_off[d] + atomicAdd(&g_cur[d], 1);
    g_eidx[pos] = g_src[e];
}

// ---------------------------------------------------------------------------
// K3: y = dinv ⊙ (x @ W1).  32 rows × 64 cols per block, 128 threads, 4x4 tile.
__global__ __launch_bounds__(128) void k_gemm1(const float* __restrict__ x,
                                               const float* __restrict__ W1) {
    __shared__ float xs[32 * 128];   // 16 KB
    __shared__ float ws[128 * 64];   // 32 KB
    int tid = threadIdx.x;
    size_t rowbase = (size_t)blockIdx.x * 32;

    const float4* x4 = (const float4*)(x + rowbase * IN_F);
    float4* xs4 = (float4*)xs;
#pragma unroll
    for (int it = 0; it < 8; it++) xs4[tid + it * 128] = x4[tid + it * 128];
    const float4* w4 = (const float4*)W1;
    float4* ws4 = (float4*)ws;
#pragma unroll
    for (int it = 0; it < 16; it++) ws4[tid + it * 128] = w4[tid + it * 128];
    __syncthreads();

    int jg = tid & 15, mg = tid >> 4;
    int j0 = jg * 4, m0 = mg * 4;
    float acc[4][4] = {};
#pragma unroll 8
    for (int k = 0; k < 128; k++) {
        float4 b = *(const float4*)&ws[k * 64 + j0];
#pragma unroll
        for (int i = 0; i < 4; i++) {
            float a = xs[(m0 + i) * 128 + k];
            acc[i][0] += a * b.x; acc[i][1] += a * b.y;
            acc[i][2] += a * b.z; acc[i][3] += a * b.w;
        }
    }
#pragma unroll
    for (int i = 0; i < 4; i++) {
        size_t row = rowbase + m0 + i;
        float dv = g_dinv[row];
        float4 o = make_float4(acc[i][0] * dv, acc[i][1] * dv,
                               acc[i][2] * dv, acc[i][3] * dv);
        *(float4*)&g_y[row * H_F + j0] = o;
    }
}

// ---------------------------------------------------------------------------
// K4/K6: CSR propagate, atomic-free. One warp per (node, 32-feature half):
// register accumulate over the node's incoming edges, single coalesced store.
// PASS=0: acc over g_y, epilogue z = dinv*relu(dinv*(acc+y[n]) + b1).
// PASS=1: acc over g_z, epilogue g = dinv*(acc+z[n]).
template <int PASS>
__global__ void k_prop_csr(const float* __restrict__ b1) {
    int w = (blockIdx.x * blockDim.x + threadIdx.x) >> 5;
    int lane = threadIdx.x & 31;
    int n = w >> 1;
    if (n >= Nn) return;
    int h = (w & 1) << 5;
    const float* val = (PASS == 0) ? g_y : g_z;
    int beg = g_off[n];
    int cnt = g_cnt[n];
    float acc = 0.f;
    for (int j = 0; j < cnt; j++) {
        int s = __ldg(&g_eidx[beg + j]);
        acc += __ldg(&val[(size_t)s * H_F + h + lane]);
    }
    float dv = g_dinv[n];
    size_t self = (size_t)n * H_F + h + lane;
    if (PASS == 0) {
        float hh = fmaf(dv, acc + g_y[self], b1[h + lane]);
        g_z[self] = dv * fmaxf(hh, 0.f);
    } else {
        g_g[self] = dv * (acc + g_z[self]);
    }
}

// ---------------------------------------------------------------------------
// K7: mu = g@Wmu + bmu; log = g@Wlog + blog (g precomputed by pass 1).
__global__ __launch_bounds__(128) void k_final(const float* __restrict__ Wmu,
                                               const float* __restrict__ bmu,
                                               const float* __restrict__ Wlog,
                                               const float* __restrict__ blog,
                                               float* __restrict__ out) {
    __shared__ float gs[32 * 64];   // 8 KB
    __shared__ float wc[64 * 64];   // 16 KB
    __shared__ float bc[64];
    int tid = threadIdx.x;
    size_t nb = (size_t)blockIdx.x * 32;

    for (int i = tid; i < 64 * 64; i += 128) {
        int k = i >> 6, j = i & 63;
        wc[i] = (j < 32) ? Wmu[k * 32 + j] : Wlog[k * 32 + (j - 32)];
    }
    if (tid < 64) bc[tid] = (tid < 32) ? bmu[tid] : blog[tid - 32];
    {
        const float4* g4 = (const float4*)&g_g[nb * H_F];
        float4* gs4 = (float4*)gs;
#pragma unroll
        for (int it = 0; it < 4; it++) gs4[tid + it * 128] = g4[tid + it * 128];
    }
    __syncthreads();

    int jg = tid & 15, mg = tid >> 4;
    int j0 = jg * 4, m0 = mg * 4;
    float acc[4][4] = {};
#pragma unroll 8
    for (int k = 0; k < 64; k++) {
        float4 b = *(const float4*)&wc[k * 64 + j0];
#pragma unroll
        for (int i = 0; i < 4; i++) {
            float a = gs[(m0 + i) * 64 + k];
            acc[i][0] += a * b.x; acc[i][1] += a * b.y;
            acc[i][2] += a * b.z; acc[i][3] += a * b.w;
        }
    }
#pragma unroll
    for (int i = 0; i < 4; i++) {
        size_t n = nb + m0 + i;
        float4 o = make_float4(acc[i][0] + bc[j0], acc[i][1] + bc[j0 + 1],
                               acc[i][2] + bc[j0 + 2], acc[i][3] + bc[j0 + 3]);
        float* dp = (j0 < 32)
            ? (out + n * OUT_F + j0)
            : (out + (size_t)Nn * OUT_F + n * OUT_F + (j0 - 32));
        *(float4*)dp = o;
    }
}

// ---------------------------------------------------------------------------
extern "C" void kernel_launch(void* const* d_in, const int* in_sizes, int n_in,
                              void* d_out, int out_size) {
    const float* x    = (const float*)d_in[0];
    const void*  ei   = d_in[1];                 // [2, E] int32 OR int64
    const float* W1   = (const float*)d_in[2];
    const float* b1   = (const float*)d_in[3];
    const float* Wmu  = (const float*)d_in[4];
    const float* bmu  = (const float*)d_in[5];
    const float* Wlog = (const float*)d_in[6];
    const float* blog = (const float*)d_in[7];
    float*       out  = (float*)d_out;

    int E = in_sizes[1] / 2;

    k_detect<<<1, 256>>>((const int*)ei);
    k_zero<<<NB, 256>>>();
    k_cvt_hist<<<(E + 255) / 256, 256>>>(ei, E);
    k_scan1<<<NB, 256>>>();
    k_scan2<<<1, 512>>>();
    k_scan3<<<NB, 256>>>();
    k_scatter<<<(E + 255) / 256, 256>>>(E);
    k_gemm1<<<Nn / 32, 128>>>(x, W1);
    {
        int warps = Nn * 2;                       // (node, half)
        int blocks = (warps * 32 + 255) / 256;
        k_prop_csr<0><<<blocks, 256>>>(b1);
        k_prop_csr<1><<<blocks, 256>>>(b1);
    }
    k_final<<<Nn / 32, 128>>>(Wmu, bmu, Wlog, blog, out);
}

// round 16
// speedup vs baseline: 2.5538x; 1.1371x over previous
#include <cuda_runtime.h>
#include <cuda_bf16.h>
#include <cstdint>

// Problem constants (fixed by the dataset).
#define Nn 100000
#define Ee 1600000
#define IN_F 128
#define H_F 64
#define OUT_F 32
#define NB 391            // ceil(Nn/256)

static_assert(Nn % 32 == 0, "row tiling assumes N % 32 == 0");

// Scratch (static __device__ — no allocation allowed).
// NOTE: referenced ONLY from device code (host symbol-passing is the ATS trap
// that silently reads host shadows on GB300).
__device__ __align__(256) float g_dinv[Nn];
__device__ __align__(256) float g_y   [(size_t)Nn * H_F];
__device__ __align__(256) float g_z   [(size_t)Nn * H_F];
__device__ __align__(256) float g_g   [(size_t)Nn * H_F];
__device__ __align__(256) int   g_src [Ee];
__device__ __align__(256) int   g_dst [Ee];
__device__ __align__(256) int   g_eidx[Ee];       // CSR: src ids grouped by dst
__device__ __align__(256) int   g_cnt [Nn];
__device__ __align__(256) int   g_off [Nn];
__device__ __align__(256) int   g_cur [Nn];
__device__ __align__(256) int   g_bsum[NB];
__device__ __align__(256) int   g_bpre[NB];
__device__ int g_is64;

// ---------------------------------------------------------------------------
// KD: detect edge_index dtype (int64 ids < 2^31 -> odd 32-bit words all 0).
__global__ void k_detect(const int* __restrict__ ei) {
    __shared__ int nz;
    if (threadIdx.x == 0) nz = 0;
    __syncthreads();
    int acc = 0;
#pragma unroll
    for (int k = 0; k < 8; k++) {
        int i = threadIdx.x * 8 + k;      // [0, 2048)
        acc |= ei[2 * i + 1];
    }
    if (acc) atomicOr(&nz, 1);
    __syncthreads();
    if (threadIdx.x == 0) g_is64 = (nz == 0) ? 1 : 0;
}

// KZ: zero the histogram (graph replays reuse state; must re-zero each call).
__global__ void k_zero() {
    int i = blockIdx.x * blockDim.x + threadIdx.x;
    if (i < Nn) g_cnt[i] = 0;
}

// KC: convert indices to int32 + in-degree histogram (fused).
__global__ void k_cvt_hist(const void* __restrict__ ei, int E) {
    int e = blockIdx.x * blockDim.x + threadIdx.x;
    if (e >= E) return;
    int s, d;
    if (g_is64) {
        const long long* p = (const long long*)ei;
        s = (int)p[e]; d = (int)p[E + e];
    } else {
        const int* p = (const int*)ei;
        s = p[e]; d = p[E + e];
    }
    g_src[e] = s;
    g_dst[e] = d;
    atomicAdd(&g_cnt[d], 1);
}

// ---------------------------------------------------------------------------
// S1: per-256-tile exclusive scan of g_cnt -> g_off, tile totals -> g_bsum.
__global__ void k_scan1() {
    __shared__ int sh[256];
    int i = blockIdx.x * 256 + threadIdx.x;
    int v = (i < Nn) ? g_cnt[i] : 0;
    sh[threadIdx.x] = v;
    __syncthreads();
#pragma unroll
    for (int off = 1; off < 256; off <<= 1) {
        int t = (threadIdx.x >= off) ? sh[threadIdx.x - off] : 0;
        __syncthreads();
        sh[threadIdx.x] += t;
        __syncthreads();
    }
    if (i < Nn) g_off[i] = sh[threadIdx.x] - v;     // exclusive
    if (threadIdx.x == 255) g_bsum[blockIdx.x] = sh[255];
}

// S2: single-block exclusive scan of the NB tile totals.
__global__ void k_scan2() {
    __shared__ int sh[512];
    int v = (threadIdx.x < NB) ? g_bsum[threadIdx.x] : 0;
    sh[threadIdx.x] = v;
    __syncthreads();
#pragma unroll
    for (int off = 1; off < 512; off <<= 1) {
        int t = (threadIdx.x >= off) ? sh[threadIdx.x - off] : 0;
        __syncthreads();
        sh[threadIdx.x] += t;
        __syncthreads();
    }
    if (threadIdx.x < NB) g_bpre[threadIdx.x] = sh[threadIdx.x] - v;
}

// S3: finalize offsets; zero cursors; dinv = rsqrt(deg+1) (self loop).
__global__ void k_scan3() {
    int i = blockIdx.x * blockDim.x + threadIdx.x;
    if (i >= Nn) return;
    g_off[i] += g_bpre[blockIdx.x];
    g_cur[i] = 0;
    g_dinv[i] = rsqrtf((float)g_cnt[i] + 1.0f);
}

// KS: scatter src ids into dst-grouped CSR slots.
__global__ void k_scatter(int E) {
    int e = blockIdx.x * blockDim.x + threadIdx.x;
    if (e >= E) return;
    int d = g_dst[e];
    int pos = g_off[d] + atomicAdd(&g_cur[d], 1);
    g_eidx[pos] = g_src[e];
}

// ---------------------------------------------------------------------------
// K3: y = dinv ⊙ (x @ W1).  32 rows × 64 cols per block, 128 threads, 4x4 tile.
__global__ __launch_bounds__(128) void k_gemm1(const float* __restrict__ x,
                                               const float* __restrict__ W1) {
    __shared__ float xs[32 * 128];   // 16 KB
    __shared__ float ws[128 * 64];   // 32 KB
    int tid = threadIdx.x;
    size_t rowbase = (size_t)blockIdx.x * 32;

    const float4* x4 = (const float4*)(x + rowbase * IN_F);
    float4* xs4 = (float4*)xs;
#pragma unroll
    for (int it = 0; it < 8; it++) xs4[tid + it * 128] = x4[tid + it * 128];
    const float4* w4 = (const float4*)W1;
    float4* ws4 = (float4*)ws;
#pragma unroll
    for (int it = 0; it < 16; it++) ws4[tid + it * 128] = w4[tid + it * 128];
    __syncthreads();

    int jg = tid & 15, mg = tid >> 4;
    int j0 = jg * 4, m0 = mg * 4;
    float acc[4][4] = {};
#pragma unroll 8
    for (int k = 0; k < 128; k++) {
        float4 b = *(const float4*)&ws[k * 64 + j0];
#pragma unroll
        for (int i = 0; i < 4; i++) {
            float a = xs[(m0 + i) * 128 + k];
            acc[i][0] += a * b.x; acc[i][1] += a * b.y;
            acc[i][2] += a * b.z; acc[i][3] += a * b.w;
        }
    }
#pragma unroll
    for (int i = 0; i < 4; i++) {
        size_t row = rowbase + m0 + i;
        float dv = g_dinv[row];
        float4 o = make_float4(acc[i][0] * dv, acc[i][1] * dv,
                               acc[i][2] * dv, acc[i][3] * dv);
        *(float4*)&g_y[row * H_F + j0] = o;
    }
}

// ---------------------------------------------------------------------------
// K4/K6: CSR propagate, atomic-free. ONE warp per node, float2 per lane
// (lane covers features 2*lane, 2*lane+1): per edge one broadcast index load
// + one LDG.64 per lane (256B/warp contiguous). Edge loop unrolled x4 with
// independent partial sums for MLP>=4 (hides L2 latency).
// PASS=0: acc over g_y, epilogue z = dinv*relu(dinv*(acc+y[n]) + b1).
// PASS=1: acc over g_z, epilogue g = dinv*(acc+z[n]).
template <int PASS>
__global__ void k_prop_csr(const float* __restrict__ b1) {
    int n = (blockIdx.x * blockDim.x + threadIdx.x) >> 5;
    int lane = threadIdx.x & 31;
    if (n >= Nn) return;
    const float2* val = (const float2*)((PASS == 0) ? g_y : g_z);
    int beg = g_off[n];
    int cnt = g_cnt[n];

    float2 a0 = {0.f, 0.f}, a1 = {0.f, 0.f}, a2 = {0.f, 0.f}, a3 = {0.f, 0.f};
    int j = 0;
    for (; j + 4 <= cnt; j += 4) {
        int s0 = __ldg(&g_eidx[beg + j + 0]);
        int s1 = __ldg(&g_eidx[beg + j + 1]);
        int s2 = __ldg(&g_eidx[beg + j + 2]);
        int s3 = __ldg(&g_eidx[beg + j + 3]);
        float2 v0 = __ldg(&val[(size_t)s0 * 32 + lane]);
        float2 v1 = __ldg(&val[(size_t)s1 * 32 + lane]);
        float2 v2 = __ldg(&val[(size_t)s2 * 32 + lane]);
        float2 v3 = __ldg(&val[(size_t)s3 * 32 + lane]);
        a0.x += v0.x; a0.y += v0.y;
        a1.x += v1.x; a1.y += v1.y;
        a2.x += v2.x; a2.y += v2.y;
        a3.x += v3.x; a3.y += v3.y;
    }
    for (; j < cnt; j++) {
        int s = __ldg(&g_eidx[beg + j]);
        float2 v = __ldg(&val[(size_t)s * 32 + lane]);
        a0.x += v.x; a0.y += v.y;
    }
    float accx = (a0.x + a1.x) + (a2.x + a3.x);
    float accy = (a0.y + a1.y) + (a2.y + a3.y);

    float dv = g_dinv[n];
    size_t self = (size_t)n * 32 + lane;           // float2 units
    if (PASS == 0) {
        float2 ys = ((const float2*)g_y)[self];
        float2 bb = __ldg(&((const float2*)b1)[lane]);
        float hx = fmaf(dv, accx + ys.x, bb.x);
        float hy = fmaf(dv, accy + ys.y, bb.y);
        float2 o = make_float2(dv * fmaxf(hx, 0.f), dv * fmaxf(hy, 0.f));
        ((float2*)g_z)[self] = o;
    } else {
        float2 zs = ((const float2*)g_z)[self];
        float2 o = make_float2(dv * (accx + zs.x), dv * (accy + zs.y));
        ((float2*)g_g)[self] = o;
    }
}

// ---------------------------------------------------------------------------
// K7: mu = g@Wmu + bmu; log = g@Wlog + blog (g precomputed by pass 1).
__global__ __launch_bounds__(128) void k_final(const float* __restrict__ Wmu,
                                               const float* __restrict__ bmu,
                                               const float* __restrict__ Wlog,
                                               const float* __restrict__ blog,
                                               float* __restrict__ out) {
    __shared__ float gs[32 * 64];   // 8 KB
    __shared__ float wc[64 * 64];   // 16 KB
    __shared__ float bc[64];
    int tid = threadIdx.x;
    size_t nb = (size_t)blockIdx.x * 32;

    for (int i = tid; i < 64 * 64; i += 128) {
        int k = i >> 6, j = i & 63;
        wc[i] = (j < 32) ? Wmu[k * 32 + j] : Wlog[k * 32 + (j - 32)];
    }
    if (tid < 64) bc[tid] = (tid < 32) ? bmu[tid] : blog[tid - 32];
    {
        const float4* g4 = (const float4*)&g_g[nb * H_F];
        float4* gs4 = (float4*)gs;
#pragma unroll
        for (int it = 0; it < 4; it++) gs4[tid + it * 128] = g4[tid + it * 128];
    }
    __syncthreads();

    int jg = tid & 15, mg = tid >> 4;
    int j0 = jg * 4, m0 = mg * 4;
    float acc[4][4] = {};
#pragma unroll 8
    for (int k = 0; k < 64; k++) {
        float4 b = *(const float4*)&wc[k * 64 + j0];
#pragma unroll
        for (int i = 0; i < 4; i++) {
            float a = gs[(m0 + i) * 64 + k];
            acc[i][0] += a * b.x; acc[i][1] += a * b.y;
            acc[i][2] += a * b.z; acc[i][3] += a * b.w;
        }
    }
#pragma unroll
    for (int i = 0; i < 4; i++) {
        size_t n = nb + m0 + i;
        float4 o = make_float4(acc[i][0] + bc[j0], acc[i][1] + bc[j0 + 1],
                               acc[i][2] + bc[j0 + 2], acc[i][3] + bc[j0 + 3]);
        float* dp = (j0 < 32)
            ? (out + n * OUT_F + j0)
            : (out + (size_t)Nn * OUT_F + n * OUT_F + (j0 - 32));
        *(float4*)dp = o;
    }
}

// ---------------------------------------------------------------------------
extern "C" void kernel_launch(void* const* d_in, const int* in_sizes, int n_in,
                              void* d_out, int out_size) {
    const float* x    = (const float*)d_in[0];
    const void*  ei   = d_in[1];                 // [2, E] int32 OR int64
    const float* W1   = (const float*)d_in[2];
    const float* b1   = (const float*)d_in[3];
    const float* Wmu  = (const float*)d_in[4];
    const float* bmu  = (const float*)d_in[5];
    const float* Wlog = (const float*)d_in[6];
    const float* blog = (const float*)d_in[7];
    float*       out  = (float*)d_out;

    int E = in_sizes[1] / 2;

    k_detect<<<1, 256>>>((const int*)ei);
    k_zero<<<NB, 256>>>();
    k_cvt_hist<<<(E + 255) / 256, 256>>>(ei, E);
    k_scan1<<<NB, 256>>>();
    k_scan2<<<1, 512>>>();
    k_scan3<<<NB, 256>>>();
    k_scatter<<<(E + 255) / 256, 256>>>(E);
    k_gemm1<<<Nn / 32, 128>>>(x, W1);
    {
        int blocks = (Nn * 32 + 255) / 256;       // one warp per node
        k_prop_csr<0><<<blocks, 256>>>(b1);
        k_prop_csr<1><<<blocks, 256>>>(b1);
    }
    k_final<<<Nn / 32, 128>>>(Wmu, bmu, Wlog, blog, out);
}